// round 15
// baseline (speedup 1.0000x reference)
#include <cuda_runtime.h>
#include <cstdint>

#define NN 50000
#define EE 800000
#define DD 128
#define NG 64
#define SCAN_CHUNK 1024
#define NCHUNK ((NN + SCAN_CHUNK - 1) / SCAN_CHUNK)   // 49
#define FTILE 64
#define FTHREADS 256
#define UPAD 132

// -------- scratch (device globals: no allocation allowed) --------
__device__ __align__(16) float g_tmpA[NN * DD];  // gemm0 output
__device__ __align__(16) float g_h1[NN * DD];    // layer-0 output (post-relu)
__device__ __align__(16) float g_h2[NN * DD];    // layer-1 output (post-relu)
__device__ __align__(16) float g_dinv[NN];
__device__ __align__(16) float g_cnt[NG];
__device__ __align__(16) int   g_degi[NN];
__device__ __align__(16) int   g_rowptr[NN + 1];
__device__ __align__(16) int   g_cursor[NN];
__device__ __align__(16) int2  g_csr[EE];        // {src, norm-as-int}
__device__ __align__(16) int   g_bsum[NCHUNK];

// ================= prep (R8-proven) =================
__global__ void k_zero(float* __restrict__ out) {
    int i = blockIdx.x * blockDim.x + threadIdx.x;
    if (i < NN) g_degi[i] = 0;
    if (i < NG * DD) out[i] = 0.f;
}

__global__ void k_deg_count(const int* __restrict__ ei) {
    int e = blockIdx.x * blockDim.x + threadIdx.x;
    if (e < EE) atomicAdd(&g_degi[ei[EE + e]], 1);
}

__global__ void k_scan1() {
    __shared__ int wsum[32];
    int tid = threadIdx.x, lane = tid & 31, wd = tid >> 5;
    int i = blockIdx.x * SCAN_CHUNK + tid;
    int v = (i < NN) ? g_degi[i] : 0;
    int x = v;
#pragma unroll
    for (int o = 1; o < 32; o <<= 1) {
        int y = __shfl_up_sync(0xffffffffu, x, o);
        if (lane >= o) x += y;
    }
    if (lane == 31) wsum[wd] = x;
    __syncthreads();
    if (wd == 0) {
        int s = wsum[lane];
#pragma unroll
        for (int o = 1; o < 32; o <<= 1) {
            int y = __shfl_up_sync(0xffffffffu, s, o);
            if (lane >= o) s += y;
        }
        wsum[lane] = s;
    }
    __syncthreads();
    int excl = (wd ? wsum[wd - 1] : 0) + x - v;
    if (i < NN) g_rowptr[i] = excl;
    if (tid == SCAN_CHUNK - 1) g_bsum[blockIdx.x] = wsum[31];
}

__global__ void k_scan3(const int* __restrict__ batch) {
    __shared__ int pref[NCHUNK];
    int tid = threadIdx.x;
    if (tid == 0) {
        int run = 0;
#pragma unroll 1
        for (int j = 0; j < NCHUNK; j++) {
            int t = g_bsum[j];
            pref[j] = run;
            run += t;
        }
    }
    __syncthreads();
    int i = blockIdx.x * blockDim.x + tid;
    if (i < NN) {
        int rp = g_rowptr[i] + pref[i / SCAN_CHUNK];
        g_rowptr[i] = rp;
        g_cursor[i] = rp;
        g_dinv[i] = rsqrtf((float)(g_degi[i] + 1));
    }
    if (i == 0) g_rowptr[NN] = EE;
    if (blockIdx.x == 0 && tid < NG) {
        int g = tid;
        int lo = 0, hi = NN;
        while (lo < hi) { int m = (lo + hi) >> 1; if (batch[m] < g) lo = m + 1; else hi = m; }
        int start = lo;
        lo = 0; hi = NN;
        while (lo < hi) { int m = (lo + hi) >> 1; if (batch[m] <= g) lo = m + 1; else hi = m; }
        g_cnt[g] = (float)(lo - start);
    }
}

__global__ void k_csr_fill(const int* __restrict__ ei) {
    int e = blockIdx.x * blockDim.x + threadIdx.x;
    if (e < EE) {
        int s = ei[e];
        int d = ei[EE + e];
        int pos = atomicAdd(&g_cursor[d], 1);
        float nm = g_dinv[s] * g_dinv[d];
        g_csr[pos] = make_int2(s, __float_as_int(nm));
    }
}

// ================= GEMM for layer 0 (R8-proven, relu_in=0): tmpA = x @ W0 =================
__global__ __launch_bounds__(128, 4)
void k_gemm(const float* __restrict__ A, const float* __restrict__ W,
            float* __restrict__ C) {
    __shared__ float As[2][16][68];
    __shared__ float Ws[2][16][128];

    int tid = threadIdx.x;
    int tx = tid & 15;
    int ty = tid >> 4;
    int row0 = blockIdx.x * 64;

    unsigned long long acc[8][4];
#pragma unroll
    for (int i = 0; i < 8; i++)
#pragma unroll
        for (int j = 0; j < 4; j++) acc[i][j] = 0ull;

    float4 aR[2];
    float4 wR[4];

    auto loadT = [&](int kt) {
#pragma unroll
        for (int q = 0; q < 2; q++) {
            int id = tid + q * 128;
            int r = id >> 2;
            int kc = (id & 3) * 4;
            int grow = row0 + r;
            float4 v = make_float4(0.f, 0.f, 0.f, 0.f);
            if (grow < NN) v = *(const float4*)&A[(size_t)grow * DD + kt * 16 + kc];
            aR[q] = v;
        }
#pragma unroll
        for (int q = 0; q < 4; q++) {
            int id = tid + q * 128;
            wR[q] = ((const float4*)&W[kt * 16 * DD])[id];
        }
    };
    auto stsT = [&](int b) {
#pragma unroll
        for (int q = 0; q < 2; q++) {
            int id = tid + q * 128;
            int r = id >> 2;
            int kc = (id & 3) * 4;
            As[b][kc + 0][r] = aR[q].x;
            As[b][kc + 1][r] = aR[q].y;
            As[b][kc + 2][r] = aR[q].z;
            As[b][kc + 3][r] = aR[q].w;
        }
#pragma unroll
        for (int q = 0; q < 4; q++) {
            int id = tid + q * 128;
            ((float4*)Ws[b])[id] = wR[q];
        }
    };

    loadT(0);
    stsT(0);
    __syncthreads();

    for (int kt = 0; kt < 8; kt++) {
        if (kt < 7) loadT(kt + 1);
        int b = kt & 1;
#pragma unroll
        for (int k = 0; k < 16; k++) {
            float4 a0 = *(float4*)&As[b][k][ty * 8];
            float4 a1 = *(float4*)&As[b][k][ty * 8 + 4];
            ulonglong2 w0 = *(ulonglong2*)&Ws[b][k][tx * 8];
            ulonglong2 w1 = *(ulonglong2*)&Ws[b][k][tx * 8 + 4];
            unsigned long long wp[4] = {w0.x, w0.y, w1.x, w1.y};
            float av[8] = {a0.x, a0.y, a0.z, a0.w, a1.x, a1.y, a1.z, a1.w};
#pragma unroll
            for (int i = 0; i < 8; i++) {
                unsigned long long ap;
                asm("mov.b64 %0, {%1, %1};" : "=l"(ap) : "r"(__float_as_uint(av[i])));
#pragma unroll
                for (int j = 0; j < 4; j++) {
                    asm("fma.rn.f32x2 %0, %1, %2, %0;"
                        : "+l"(acc[i][j]) : "l"(ap), "l"(wp[j]));
                }
            }
        }
        if (kt < 7) {
            stsT((kt + 1) & 1);
            __syncthreads();
        }
    }

#pragma unroll
    for (int i = 0; i < 8; i++) {
        int grow = row0 + ty * 8 + i;
        if (grow < NN) {
            float o[8];
#pragma unroll
            for (int j = 0; j < 4; j++) {
                unsigned int lo, hi;
                asm("mov.b64 {%0, %1}, %2;" : "=r"(lo), "=r"(hi) : "l"(acc[i][j]));
                o[2 * j] = __uint_as_float(lo);
                o[2 * j + 1] = __uint_as_float(hi);
            }
            *(float4*)&C[(size_t)grow * DD + tx * 8] = make_float4(o[0], o[1], o[2], o[3]);
            *(float4*)&C[(size_t)grow * DD + tx * 8 + 4] = make_float4(o[4], o[5], o[6], o[7]);
        }
    }
}

// ================= layer-0 aggregation (R8-proven gather) + bias + RELU -> g_h1 =================
__global__ void k_aggR(const float* __restrict__ tmp,
                       const float* __restrict__ b,
                       float* __restrict__ hout) {
    int warp = (blockIdx.x * blockDim.x + threadIdx.x) >> 5;
    int lane = threadIdx.x & 31;
    if (warp >= NN) return;
    int d = warp;

    float di = g_dinv[d];
    float n2 = di * di;
    float4 bb = ((const float4*)b)[lane];
    float4 v = ((const float4*)tmp)[d * 32 + lane];
    float4 acc;
    acc.x = fmaf(v.x, n2, bb.x); acc.y = fmaf(v.y, n2, bb.y);
    acc.z = fmaf(v.z, n2, bb.z); acc.w = fmaf(v.w, n2, bb.w);

    int idx = g_rowptr[d];
    int end = g_rowptr[d + 1];
    for (; idx + 1 < end; idx += 2) {
        int2 c0 = g_csr[idx];
        int2 c1 = g_csr[idx + 1];
        float n0 = __int_as_float(c0.y);
        float n1 = __int_as_float(c1.y);
        float4 u0 = ((const float4*)tmp)[c0.x * 32 + lane];
        float4 u1 = ((const float4*)tmp)[c1.x * 32 + lane];
        acc.x = fmaf(u0.x, n0, acc.x); acc.y = fmaf(u0.y, n0, acc.y);
        acc.z = fmaf(u0.z, n0, acc.z); acc.w = fmaf(u0.w, n0, acc.w);
        acc.x = fmaf(u1.x, n1, acc.x); acc.y = fmaf(u1.y, n1, acc.y);
        acc.z = fmaf(u1.z, n1, acc.z); acc.w = fmaf(u1.w, n1, acc.w);
    }
    if (idx < end) {
        int2 c = g_csr[idx];
        float nm = __int_as_float(c.y);
        float4 u = ((const float4*)tmp)[c.x * 32 + lane];
        acc.x = fmaf(u.x, nm, acc.x); acc.y = fmaf(u.y, nm, acc.y);
        acc.z = fmaf(u.z, nm, acc.z); acc.w = fmaf(u.w, nm, acc.w);
    }

    acc.x = fmaxf(acc.x, 0.f); acc.y = fmaxf(acc.y, 0.f);
    acc.z = fmaxf(acc.z, 0.f); acc.w = fmaxf(acc.w, 0.f);
    ((float4*)hout)[d * 32 + lane] = acc;
}

// ================= fused layer: u = agg(hprev); out = relu(u @ W + b) =================
// (valid because segment_sum commutes with right-multiplication by W)
template <int FINAL>
__global__ __launch_bounds__(FTHREADS, 2)
void k_fused(const float* __restrict__ hprev, const float* __restrict__ W,
             const float* __restrict__ b, const int* __restrict__ batch,
             float* __restrict__ hout) {
    __shared__ float u_s[FTILE][UPAD];      // [row][k], pad 132
    __shared__ float Ws[16][DD];            // one k-tile of W

    int tid = threadIdx.x;
    int wid = tid >> 5;
    int lane = tid & 31;
    int row0 = blockIdx.x * FTILE;

    // ---- phase 1: gather 8 nodes per warp ----
#pragma unroll 1
    for (int n = 0; n < 8; n++) {
        int d = row0 + wid * 8 + n;
        if (d < NN) {
            float di = g_dinv[d];
            float n2 = di * di;
            float4 v = ((const float4*)hprev)[d * 32 + lane];
            float4 acc = make_float4(v.x * n2, v.y * n2, v.z * n2, v.w * n2);
            int idx = g_rowptr[d];
            int end = g_rowptr[d + 1];
            for (; idx + 1 < end; idx += 2) {
                int2 c0 = g_csr[idx];
                int2 c1 = g_csr[idx + 1];
                float n0 = __int_as_float(c0.y);
                float n1 = __int_as_float(c1.y);
                float4 u0 = ((const float4*)hprev)[c0.x * 32 + lane];
                float4 u1 = ((const float4*)hprev)[c1.x * 32 + lane];
                acc.x = fmaf(u0.x, n0, acc.x); acc.y = fmaf(u0.y, n0, acc.y);
                acc.z = fmaf(u0.z, n0, acc.z); acc.w = fmaf(u0.w, n0, acc.w);
                acc.x = fmaf(u1.x, n1, acc.x); acc.y = fmaf(u1.y, n1, acc.y);
                acc.z = fmaf(u1.z, n1, acc.z); acc.w = fmaf(u1.w, n1, acc.w);
            }
            if (idx < end) {
                int2 c = g_csr[idx];
                float nm = __int_as_float(c.y);
                float4 u = ((const float4*)hprev)[c.x * 32 + lane];
                acc.x = fmaf(u.x, nm, acc.x); acc.y = fmaf(u.y, nm, acc.y);
                acc.z = fmaf(u.z, nm, acc.z); acc.w = fmaf(u.w, nm, acc.w);
            }
            *(float4*)&u_s[d - row0][lane * 4] = acc;
        }
    }

    // ---- phase 2: GEMM u_s @ W, W k-tiles staged through smem (reg prefetch) ----
    float4 wRa, wRb;
    {
        const float4* p = (const float4*)&W[0];
        wRa = p[tid * 2]; wRb = p[tid * 2 + 1];
    }
    __syncthreads();                     // u_s complete
    ((float4*)Ws)[tid * 2] = wRa;
    ((float4*)Ws)[tid * 2 + 1] = wRb;
    __syncthreads();

    int tx = tid & 15;                   // col group: 8 cols
    int ty = tid >> 4;                   // row group: 4 rows
    unsigned long long acc[4][4];
#pragma unroll
    for (int i = 0; i < 4; i++)
#pragma unroll
        for (int c = 0; c < 4; c++) acc[i][c] = 0ull;

    for (int kt = 0; kt < 8; kt++) {
        if (kt < 7) {
            const float4* p = (const float4*)&W[(kt + 1) * 16 * DD];
            wRa = p[tid * 2]; wRb = p[tid * 2 + 1];
        }
#pragma unroll
        for (int kc = 0; kc < 4; kc++) {
            float4 a[4];
#pragma unroll
            for (int i = 0; i < 4; i++)
                a[i] = *(float4*)&u_s[ty * 4 + i][kt * 16 + kc * 4];
#pragma unroll
            for (int j = 0; j < 4; j++) {
                ulonglong2 wA = *(ulonglong2*)&Ws[kc * 4 + j][tx * 8];
                ulonglong2 wB = *(ulonglong2*)&Ws[kc * 4 + j][tx * 8 + 4];
                unsigned long long wp[4] = {wA.x, wA.y, wB.x, wB.y};
#pragma unroll
                for (int i = 0; i < 4; i++) {
                    float av = (j == 0) ? a[i].x : (j == 1) ? a[i].y : (j == 2) ? a[i].z : a[i].w;
                    unsigned long long ap;
                    asm("mov.b64 %0, {%1, %1};" : "=l"(ap) : "r"(__float_as_uint(av)));
#pragma unroll
                    for (int c = 0; c < 4; c++)
                        asm("fma.rn.f32x2 %0, %1, %2, %0;"
                            : "+l"(acc[i][c]) : "l"(ap), "l"(wp[c]));
                }
            }
        }
        if (kt < 7) {
            __syncthreads();
            ((float4*)Ws)[tid * 2] = wRa;
            ((float4*)Ws)[tid * 2 + 1] = wRb;
            __syncthreads();
        }
    }

    // ---- epilogue: + bias, relu, store or pool-RED ----
    float4 bb0 = ((const float4*)b)[tx * 2];
    float4 bb1 = ((const float4*)b)[tx * 2 + 1];
#pragma unroll
    for (int i = 0; i < 4; i++) {
        int grow = row0 + ty * 4 + i;
        if (grow < NN) {
            float o[8];
#pragma unroll
            for (int c = 0; c < 4; c++) {
                unsigned int lo, hi;
                asm("mov.b64 {%0, %1}, %2;" : "=r"(lo), "=r"(hi) : "l"(acc[i][c]));
                o[2 * c] = __uint_as_float(lo);
                o[2 * c + 1] = __uint_as_float(hi);
            }
            o[0] = fmaxf(o[0] + bb0.x, 0.f); o[1] = fmaxf(o[1] + bb0.y, 0.f);
            o[2] = fmaxf(o[2] + bb0.z, 0.f); o[3] = fmaxf(o[3] + bb0.w, 0.f);
            o[4] = fmaxf(o[4] + bb1.x, 0.f); o[5] = fmaxf(o[5] + bb1.y, 0.f);
            o[6] = fmaxf(o[6] + bb1.z, 0.f); o[7] = fmaxf(o[7] + bb1.w, 0.f);
            if (FINAL) {
                int g = batch[grow];
                float* p0 = &hout[g * DD + tx * 8];
                asm volatile("red.global.add.v4.f32 [%0], {%1, %2, %3, %4};"
                             :: "l"(p0), "f"(o[0]), "f"(o[1]), "f"(o[2]), "f"(o[3]) : "memory");
                asm volatile("red.global.add.v4.f32 [%0], {%1, %2, %3, %4};"
                             :: "l"(p0 + 4), "f"(o[4]), "f"(o[5]), "f"(o[6]), "f"(o[7]) : "memory");
            } else {
                *(float4*)&hout[(size_t)grow * DD + tx * 8] = make_float4(o[0], o[1], o[2], o[3]);
                *(float4*)&hout[(size_t)grow * DD + tx * 8 + 4] = make_float4(o[4], o[5], o[6], o[7]);
            }
        }
    }
}

__global__ void k_pool_div(float* __restrict__ out) {
    int i = blockIdx.x * blockDim.x + threadIdx.x;
    if (i < NG * DD) out[i] /= fmaxf(g_cnt[i >> 7], 1.0f);
}

// ================= launch =================
extern "C" void kernel_launch(void* const* d_in, const int* in_sizes, int n_in,
                              void* d_out, int out_size) {
    const float* x = (const float*)d_in[0];
    const int* ei = (const int*)d_in[1];      // int32 (JAX x64 disabled)
    const int* batch = (const int*)d_in[2];
    const float* W0 = (const float*)d_in[3];
    const float* b0 = (const float*)d_in[4];
    const float* W1 = (const float*)d_in[5];
    const float* b1 = (const float*)d_in[6];
    const float* W2 = (const float*)d_in[7];
    const float* b2 = (const float*)d_in[8];
    float* out = (float*)d_out;

    float* tmpA; cudaGetSymbolAddress((void**)&tmpA, g_tmpA);
    float* h1;   cudaGetSymbolAddress((void**)&h1, g_h1);
    float* h2;   cudaGetSymbolAddress((void**)&h2, g_h2);

    const int TB = 256;
    int nodeB = (NN + TB - 1) / TB;
    int edgeB = (EE + TB - 1) / TB;
    int gemmB = (NN + 63) / 64;        // 782
    int aggB = (NN * 32 + TB - 1) / TB;
    int fusedB = (NN + FTILE - 1) / FTILE;  // 782

    cudaStream_t s2;
    cudaStreamCreateWithFlags(&s2, cudaStreamNonBlocking);
    cudaEvent_t evFork, evG0;
    cudaEventCreateWithFlags(&evFork, cudaEventDisableTiming);
    cudaEventCreateWithFlags(&evG0, cudaEventDisableTiming);

    // ---- fork: gemm0 (x @ W0) on s2 concurrent with graph prep on s0 ----
    cudaEventRecord(evFork, 0);
    cudaStreamWaitEvent(s2, evFork, 0);
    k_gemm<<<gemmB, 128, 0, s2>>>(x, W0, tmpA);
    cudaEventRecord(evG0, s2);

    k_zero<<<nodeB, TB>>>(out);
    k_deg_count<<<edgeB, TB>>>(ei);
    k_scan1<<<NCHUNK, SCAN_CHUNK>>>();
    k_scan3<<<nodeB, TB>>>(batch);
    k_csr_fill<<<edgeB, TB>>>(ei);

    cudaStreamWaitEvent(0, evG0, 0);

    // ---- layer 0: aggregate gemm0 output, +b0, relu -> h1 ----
    k_aggR<<<aggB, TB>>>(tmpA, b0, h1);
    // ---- layer 1 fused: h2 = relu(agg(h1) @ W1 + b1) ----
    k_fused<0><<<fusedB, FTHREADS>>>(h1, W1, b1, batch, h2);
    // ---- layer 2 fused + pool: out += relu(agg(h2) @ W2 + b2) per graph ----
    k_fused<1><<<fusedB, FTHREADS>>>(h2, W2, b2, batch, out);

    k_pool_div<<<(NG * DD + TB - 1) / TB, TB>>>(out);
}

// round 16
// speedup vs baseline: 1.0165x; 1.0165x over previous
#include <cuda_runtime.h>
#include <cuda_bf16.h>
#include <cstdint>

#define NN 50000
#define EE 800000
#define DD 128
#define NG 64
#define SCAN_CHUNK 1024
#define NCHUNK ((NN + SCAN_CHUNK - 1) / SCAN_CHUNK)   // 49

// -------- scratch (device globals: no allocation allowed) --------
__device__ __align__(16) __nv_bfloat16 g_tmpb[NN * DD]; // h @ W result (bf16)
__device__ __align__(16) float g_h[NN * DD];     // aggregated layer output (fp32)
__device__ __align__(16) float g_dinv[NN];       // rsqrt(degree)
__device__ __align__(16) float g_cnt[NG];        // pool counts
__device__ __align__(16) int   g_degi[NN];       // int in-degree (no self loop)
__device__ __align__(16) int   g_rowptr[NN + 1]; // CSR row pointers (by dst)
__device__ __align__(16) int   g_cursor[NN];     // scatter cursors
__device__ __align__(16) int2  g_csr[EE];        // {src, norm-as-int}
__device__ __align__(16) int   g_bsum[NCHUNK];   // per-chunk totals (from scan1)

// ================= prep (R8-proven) =================
__global__ void k_zero(float* __restrict__ out) {
    int i = blockIdx.x * blockDim.x + threadIdx.x;
    if (i < NN) g_degi[i] = 0;
    if (i < NG * DD) out[i] = 0.f;
}

__global__ void k_deg_count(const int* __restrict__ ei) {
    int e = blockIdx.x * blockDim.x + threadIdx.x;
    if (e < EE) atomicAdd(&g_degi[ei[EE + e]], 1);
}

__global__ void k_scan1() {
    __shared__ int wsum[32];
    int tid = threadIdx.x, lane = tid & 31, wd = tid >> 5;
    int i = blockIdx.x * SCAN_CHUNK + tid;
    int v = (i < NN) ? g_degi[i] : 0;
    int x = v;
#pragma unroll
    for (int o = 1; o < 32; o <<= 1) {
        int y = __shfl_up_sync(0xffffffffu, x, o);
        if (lane >= o) x += y;
    }
    if (lane == 31) wsum[wd] = x;
    __syncthreads();
    if (wd == 0) {
        int s = wsum[lane];
#pragma unroll
        for (int o = 1; o < 32; o <<= 1) {
            int y = __shfl_up_sync(0xffffffffu, s, o);
            if (lane >= o) s += y;
        }
        wsum[lane] = s;
    }
    __syncthreads();
    int excl = (wd ? wsum[wd - 1] : 0) + x - v;
    if (i < NN) g_rowptr[i] = excl;
    if (tid == SCAN_CHUNK - 1) g_bsum[blockIdx.x] = wsum[31];
}

__global__ void k_scan3(const int* __restrict__ batch) {
    __shared__ int pref[NCHUNK];
    int tid = threadIdx.x;
    if (tid == 0) {
        int run = 0;
#pragma unroll 1
        for (int j = 0; j < NCHUNK; j++) {
            int t = g_bsum[j];
            pref[j] = run;
            run += t;
        }
    }
    __syncthreads();
    int i = blockIdx.x * blockDim.x + tid;
    if (i < NN) {
        int rp = g_rowptr[i] + pref[i / SCAN_CHUNK];
        g_rowptr[i] = rp;
        g_cursor[i] = rp;
        g_dinv[i] = rsqrtf((float)(g_degi[i] + 1));
    }
    if (i == 0) g_rowptr[NN] = EE;
    if (blockIdx.x == 0 && tid < NG) {
        int g = tid;
        int lo = 0, hi = NN;
        while (lo < hi) { int m = (lo + hi) >> 1; if (batch[m] < g) lo = m + 1; else hi = m; }
        int start = lo;
        lo = 0; hi = NN;
        while (lo < hi) { int m = (lo + hi) >> 1; if (batch[m] <= g) lo = m + 1; else hi = m; }
        g_cnt[g] = (float)(lo - start);
    }
}

__global__ void k_csr_fill(const int* __restrict__ ei) {
    int e = blockIdx.x * blockDim.x + threadIdx.x;
    if (e < EE) {
        int s = ei[e];
        int d = ei[EE + e];
        int pos = atomicAdd(&g_cursor[d], 1);
        float nm = g_dinv[s] * g_dinv[d];
        g_csr[pos] = make_int2(s, __float_as_int(nm));
    }
}

// ================= GEMM: C_bf16[M,128] = reluOpt(A)[M,128] @ W[128,128] =================
__global__ __launch_bounds__(128, 4)
void k_gemm(const float* __restrict__ A, const float* __restrict__ W,
            __nv_bfloat16* __restrict__ C, int relu_in) {
    __shared__ float As[2][16][68];
    __shared__ float Ws[2][16][128];

    int tid = threadIdx.x;
    int tx = tid & 15;
    int ty = tid >> 4;
    int row0 = blockIdx.x * 64;

    unsigned long long acc[8][4];
#pragma unroll
    for (int i = 0; i < 8; i++)
#pragma unroll
        for (int j = 0; j < 4; j++) acc[i][j] = 0ull;

    float4 aR[2];
    float4 wR[4];

    auto loadT = [&](int kt) {
#pragma unroll
        for (int q = 0; q < 2; q++) {
            int id = tid + q * 128;
            int r = id >> 2;
            int kc = (id & 3) * 4;
            int grow = row0 + r;
            float4 v = make_float4(0.f, 0.f, 0.f, 0.f);
            if (grow < NN) v = *(const float4*)&A[(size_t)grow * DD + kt * 16 + kc];
            if (relu_in) {
                v.x = fmaxf(v.x, 0.f); v.y = fmaxf(v.y, 0.f);
                v.z = fmaxf(v.z, 0.f); v.w = fmaxf(v.w, 0.f);
            }
            aR[q] = v;
        }
#pragma unroll
        for (int q = 0; q < 4; q++) {
            int id = tid + q * 128;
            wR[q] = ((const float4*)&W[kt * 16 * DD])[id];
        }
    };
    auto stsT = [&](int b) {
#pragma unroll
        for (int q = 0; q < 2; q++) {
            int id = tid + q * 128;
            int r = id >> 2;
            int kc = (id & 3) * 4;
            As[b][kc + 0][r] = aR[q].x;
            As[b][kc + 1][r] = aR[q].y;
            As[b][kc + 2][r] = aR[q].z;
            As[b][kc + 3][r] = aR[q].w;
        }
#pragma unroll
        for (int q = 0; q < 4; q++) {
            int id = tid + q * 128;
            ((float4*)Ws[b])[id] = wR[q];
        }
    };

    loadT(0);
    stsT(0);
    __syncthreads();

    for (int kt = 0; kt < 8; kt++) {
        if (kt < 7) loadT(kt + 1);
        int b = kt & 1;
#pragma unroll
        for (int k = 0; k < 16; k++) {
            float4 a0 = *(float4*)&As[b][k][ty * 8];
            float4 a1 = *(float4*)&As[b][k][ty * 8 + 4];
            ulonglong2 w0 = *(ulonglong2*)&Ws[b][k][tx * 8];
            ulonglong2 w1 = *(ulonglong2*)&Ws[b][k][tx * 8 + 4];
            unsigned long long wp[4] = {w0.x, w0.y, w1.x, w1.y};
            float av[8] = {a0.x, a0.y, a0.z, a0.w, a1.x, a1.y, a1.z, a1.w};
#pragma unroll
            for (int i = 0; i < 8; i++) {
                unsigned long long ap;
                asm("mov.b64 %0, {%1, %1};" : "=l"(ap) : "r"(__float_as_uint(av[i])));
#pragma unroll
                for (int j = 0; j < 4; j++) {
                    asm("fma.rn.f32x2 %0, %1, %2, %0;"
                        : "+l"(acc[i][j]) : "l"(ap), "l"(wp[j]));
                }
            }
        }
        if (kt < 7) {
            stsT((kt + 1) & 1);
            __syncthreads();
        }
    }

    // epilogue: pack to bf16x2 (cvt.rn.bf16x2.f32: first src -> high half)
#pragma unroll
    for (int i = 0; i < 8; i++) {
        int grow = row0 + ty * 8 + i;
        if (grow < NN) {
            unsigned int p[4];
#pragma unroll
            for (int j = 0; j < 4; j++) {
                unsigned int lo, hi;
                asm("mov.b64 {%0, %1}, %2;" : "=r"(lo), "=r"(hi) : "l"(acc[i][j]));
                asm("cvt.rn.bf16x2.f32 %0, %1, %2;"
                    : "=r"(p[j]) : "f"(__uint_as_float(hi)), "f"(__uint_as_float(lo)));
            }
            *(uint4*)&C[(size_t)grow * DD + tx * 8] = make_uint4(p[0], p[1], p[2], p[3]);
        }
    }
}

// ================= gather aggregation: one warp per dst node (bf16 gathers) =================
// bf16 -> fp32 widening via PRMT (<<16): fixed-alu class, no slow converts.
__device__ __forceinline__ void acc_bf4(float4& acc, uint2 r, float nm) {
    unsigned int f0, f1, f2, f3;
    asm("prmt.b32 %0, %1, 0, 0x1044;" : "=r"(f0) : "r"(r.x));
    asm("prmt.b32 %0, %1, 0, 0x3244;" : "=r"(f1) : "r"(r.x));
    asm("prmt.b32 %0, %1, 0, 0x1044;" : "=r"(f2) : "r"(r.y));
    asm("prmt.b32 %0, %1, 0, 0x3244;" : "=r"(f3) : "r"(r.y));
    acc.x = fmaf(__uint_as_float(f0), nm, acc.x);
    acc.y = fmaf(__uint_as_float(f1), nm, acc.y);
    acc.z = fmaf(__uint_as_float(f2), nm, acc.z);
    acc.w = fmaf(__uint_as_float(f3), nm, acc.w);
}

template <int FINAL>
__global__ void k_agg(const float* __restrict__ b,
                      const int* __restrict__ batch,
                      float* __restrict__ out) {
    int warp = (blockIdx.x * blockDim.x + threadIdx.x) >> 5;
    int lane = threadIdx.x & 31;
    if (warp >= NN) return;
    int d = warp;

    const uint2* tp = (const uint2*)g_tmpb;   // 8B = 4 bf16 per lane-slot

    float di = g_dinv[d];
    float n2 = di * di;
    float4 acc = ((const float4*)b)[lane];
    acc_bf4(acc, tp[d * 32 + lane], n2);

    int idx = g_rowptr[d];
    int end = g_rowptr[d + 1];
    for (; idx + 1 < end; idx += 2) {
        int2 c0 = g_csr[idx];
        int2 c1 = g_csr[idx + 1];
        uint2 r0 = tp[c0.x * 32 + lane];
        uint2 r1 = tp[c1.x * 32 + lane];
        acc_bf4(acc, r0, __int_as_float(c0.y));
        acc_bf4(acc, r1, __int_as_float(c1.y));
    }
    if (idx < end) {
        int2 c = g_csr[idx];
        acc_bf4(acc, tp[c.x * 32 + lane], __int_as_float(c.y));
    }

    if (FINAL) {
        acc.x = fmaxf(acc.x, 0.f); acc.y = fmaxf(acc.y, 0.f);
        acc.z = fmaxf(acc.z, 0.f); acc.w = fmaxf(acc.w, 0.f);
        int g = batch[d];
        float* p = &out[g * DD + lane * 4];
        asm volatile("red.global.add.v4.f32 [%0], {%1, %2, %3, %4};"
                     :: "l"(p), "f"(acc.x), "f"(acc.y), "f"(acc.z), "f"(acc.w)
                     : "memory");
    } else {
        ((float4*)g_h)[d * 32 + lane] = acc;
    }
}

__global__ void k_pool_div(float* __restrict__ out) {
    int i = blockIdx.x * blockDim.x + threadIdx.x;
    if (i < NG * DD) out[i] /= fmaxf(g_cnt[i >> 7], 1.0f);
}

// ================= launch =================
extern "C" void kernel_launch(void* const* d_in, const int* in_sizes, int n_in,
                              void* d_out, int out_size) {
    const float* x = (const float*)d_in[0];
    const int* ei = (const int*)d_in[1];      // int32 (JAX x64 disabled)
    const int* batch = (const int*)d_in[2];
    const float* W0 = (const float*)d_in[3];
    const float* b0 = (const float*)d_in[4];
    const float* W1 = (const float*)d_in[5];
    const float* b1 = (const float*)d_in[6];
    const float* W2 = (const float*)d_in[7];
    const float* b2 = (const float*)d_in[8];
    float* out = (float*)d_out;

    __nv_bfloat16* tmp; cudaGetSymbolAddress((void**)&tmp, g_tmpb);
    float* h;           cudaGetSymbolAddress((void**)&h, g_h);

    const int TB = 256;
    int nodeB = (NN + TB - 1) / TB;
    int edgeB = (EE + TB - 1) / TB;
    int gemmB = (NN + 63) / 64;
    int aggB = (NN * 32 + TB - 1) / TB;

    cudaStream_t s2;
    cudaStreamCreateWithFlags(&s2, cudaStreamNonBlocking);
    cudaEvent_t evFork, evG0;
    cudaEventCreateWithFlags(&evFork, cudaEventDisableTiming);
    cudaEventCreateWithFlags(&evG0, cudaEventDisableTiming);

    // ---- fork: gemm0 on s2 concurrent with graph prep on s0 ----
    cudaEventRecord(evFork, 0);
    cudaStreamWaitEvent(s2, evFork, 0);
    k_gemm<<<gemmB, 128, 0, s2>>>(x, W0, tmp, 0);
    cudaEventRecord(evG0, s2);

    k_zero<<<nodeB, TB>>>(out);
    k_deg_count<<<edgeB, TB>>>(ei);
    k_scan1<<<NCHUNK, SCAN_CHUNK>>>();
    k_scan3<<<nodeB, TB>>>(batch);
    k_csr_fill<<<edgeB, TB>>>(ei);

    cudaStreamWaitEvent(0, evG0, 0);

    // ---- layer 0 aggregation ----
    k_agg<0><<<aggB, TB>>>(b0, batch, out);
    // ---- layer 1 ----
    k_gemm<<<gemmB, 128>>>(h, W1, tmp, 1);
    k_agg<0><<<aggB, TB>>>(b1, batch, out);
    // ---- layer 2 (fused relu + pool) ----
    k_gemm<<<gemmB, 128>>>(h, W2, tmp, 1);
    k_agg<1><<<aggB, TB>>>(b2, batch, out);

    k_pool_div<<<(NG * DD + TB - 1) / TB, TB>>>(out);
}